// round 3
// baseline (speedup 1.0000x reference)
#include <cuda_runtime.h>

// Problem constants
#define NN   65536      // nodes
#define NE   2097152    // edges
#define FIN  128
#define HID  256
#define FOUT 128
#define NG   256        // graphs
#define CAP  128        // max in-degree bucket capacity (mean 32, P(>=128) ~ 0)

// ---------------- scratch (static device globals; no runtime alloc) ----------
__device__ float g_deg[NN];
__device__ float g_dis[NN];
__device__ int   g_cnt[NN];
__device__ int   g_brow[(size_t)NN * CAP];    // 32 MB
__device__ float g_bnorm[(size_t)NN * CAP];   // 32 MB
__device__ float g_x0  [(size_t)NN * FIN];    // 32 MB
__device__ float g_agg1[(size_t)NN * FIN];    // 32 MB
__device__ float g_h1  [(size_t)NN * HID];    // 64 MB
__device__ float g_y2  [(size_t)NN * FOUT];   // 32 MB
__device__ float g_agg2[(size_t)NN * FOUT];   // 32 MB
__device__ int   g_gcnt[NG];

// ---------------- init: self-loop degree, counters, zero output --------------
__global__ void k_init(float* __restrict__ out) {
    int i = blockIdx.x * blockDim.x + threadIdx.x;
    if (i < NN) { g_deg[i] = 1.0f; g_cnt[i] = 0; }
    if (i < NG) g_gcnt[i] = 0;
    if (i < NG * FOUT) out[i] = 0.0f;
}

// ---------------- degree accumulation (target side) --------------------------
__global__ void k_deg(const int* __restrict__ ei, const float* __restrict__ ea) {
    int e = blockIdx.x * blockDim.x + threadIdx.x;
    if (e >= NE) return;
    int col = ei[NE + e];
    atomicAdd(&g_deg[col], ea[e]);
}

__global__ void k_dis() {
    int i = blockIdx.x * blockDim.x + threadIdx.x;
    if (i < NN) g_dis[i] = rsqrtf(g_deg[i]);   // deg >= 1 always (self loop)
}

// ---------------- per-graph node counts --------------------------------------
__global__ void k_count(const int* __restrict__ batch) {
    int i = blockIdx.x * blockDim.x + threadIdx.x;
    if (i < NN) atomicAdd(&g_gcnt[batch[i]], 1);
}

// ---------------- bucket build: per-target edge lists ------------------------
__global__ void k_bucket(const int* __restrict__ ei, const float* __restrict__ ea) {
    int e = blockIdx.x * blockDim.x + threadIdx.x;
    if (e >= NE) return;
    int row = ei[e];
    int col = ei[NE + e];
    float n = g_dis[row] * ea[e] * g_dis[col];
    int k = atomicAdd(&g_cnt[col], 1);
    if (k < CAP) {
        g_brow [(size_t)col * CAP + k] = row;
        g_bnorm[(size_t)col * CAP + k] = n;
    }
}

// ---------------- embedding gather -------------------------------------------
__global__ void k_gather(const float* __restrict__ chord, const int* __restrict__ nidx) {
    int t = blockIdx.x * blockDim.x + threadIdx.x;       // NN*32 threads (float4 lanes)
    if (t >= NN * 32) return;
    int i = t >> 5, l = t & 31;
    int v = nidx[i];
    ((float4*)g_x0)[(size_t)i * 32 + l] = ((const float4*)chord)[(size_t)v * 32 + l];
}

// ---------------- 128-dim gather aggregation: 1 warp per node ----------------
__device__ __forceinline__ void agg128_body(const float* __restrict__ X, float* __restrict__ Y) {
    int w = (blockIdx.x * blockDim.x + threadIdx.x) >> 5;
    if (w >= NN) return;
    int lane = threadIdx.x & 31;
    const float4* X4 = (const float4*)X;

    float d = g_dis[w];
    float s = d * d;                                   // self-loop norm
    float4 v = X4[(size_t)w * 32 + lane];
    float ax = v.x * s, ay = v.y * s, az = v.z * s, aw = v.w * s;

    int cnt = g_cnt[w]; if (cnt > CAP) cnt = CAP;
    const int*   br = g_brow  + (size_t)w * CAP;
    const float* bn = g_bnorm + (size_t)w * CAP;

    int k = 0;
    for (; k + 4 <= cnt; k += 4) {                      // 4-way MLP for L2 latency
        int r0 = br[k], r1 = br[k+1], r2 = br[k+2], r3 = br[k+3];
        float n0 = bn[k], n1 = bn[k+1], n2 = bn[k+2], n3 = bn[k+3];
        float4 u0 = X4[(size_t)r0 * 32 + lane];
        float4 u1 = X4[(size_t)r1 * 32 + lane];
        float4 u2 = X4[(size_t)r2 * 32 + lane];
        float4 u3 = X4[(size_t)r3 * 32 + lane];
        ax += n0*u0.x + n1*u1.x + n2*u2.x + n3*u3.x;
        ay += n0*u0.y + n1*u1.y + n2*u2.y + n3*u3.y;
        az += n0*u0.z + n1*u1.z + n2*u2.z + n3*u3.z;
        aw += n0*u0.w + n1*u1.w + n2*u2.w + n3*u3.w;
    }
    for (; k < cnt; k++) {
        int r = br[k]; float n = bn[k];
        float4 u = X4[(size_t)r * 32 + lane];
        ax += n*u.x; ay += n*u.y; az += n*u.z; aw += n*u.w;
    }
    ((float4*)Y)[(size_t)w * 32 + lane] = make_float4(ax, ay, az, aw);
}

__global__ void k_agg1() { agg128_body(g_x0, g_agg1); }
__global__ void k_agg2() { agg128_body(g_y2, g_agg2); }

// ---------------- tiled sgemm: C = [relu](A @ W [+ bias]) --------------------
// BM=BN=128, BK=16, 256 threads, 8x8 micro-tile. N % 128 == 0, NO % 128 == 0.
template<int K, int NO, bool BR>
__global__ void __launch_bounds__(256, 2) k_gemm(const float* __restrict__ A,
                                                 const float* __restrict__ W,
                                                 const float* __restrict__ bias,
                                                 float* __restrict__ C) {
    __shared__ float As[16][128];
    __shared__ float Bs[16][128];
    const int tid = threadIdx.x;
    const int tr = tid >> 4, tc = tid & 15;
    const int row0 = blockIdx.y * 128;
    const int col0 = blockIdx.x * 128;

    float acc[8][8];
#pragma unroll
    for (int i = 0; i < 8; i++)
#pragma unroll
        for (int j = 0; j < 8; j++) acc[i][j] = 0.0f;

    const int lrow = tid >> 1;            // A tile: row 0..127
    const int lk   = (tid & 1) * 8;       // A tile: k offset 0 or 8
    const int brow = tid >> 4;            // B tile: k row 0..15
    const int bc   = (tid & 15) * 4;      // B tile: col group

    for (int k0 = 0; k0 < K; k0 += 16) {
        float4 a0 = *(const float4*)&A[(size_t)(row0 + lrow) * K + k0 + lk];
        float4 a1 = *(const float4*)&A[(size_t)(row0 + lrow) * K + k0 + lk + 4];
        As[lk+0][lrow] = a0.x; As[lk+1][lrow] = a0.y; As[lk+2][lrow] = a0.z; As[lk+3][lrow] = a0.w;
        As[lk+4][lrow] = a1.x; As[lk+5][lrow] = a1.y; As[lk+6][lrow] = a1.z; As[lk+7][lrow] = a1.w;
        *(float4*)&Bs[brow][bc]      = *(const float4*)&W[(size_t)(k0 + brow) * NO + col0 + bc];
        *(float4*)&Bs[brow][bc + 64] = *(const float4*)&W[(size_t)(k0 + brow) * NO + col0 + bc + 64];
        __syncthreads();
#pragma unroll
        for (int kk = 0; kk < 16; kk++) {
            float4 m0 = *(float4*)&As[kk][tr * 8];
            float4 m1 = *(float4*)&As[kk][tr * 8 + 4];
            float4 n0 = *(float4*)&Bs[kk][tc * 8];
            float4 n1 = *(float4*)&Bs[kk][tc * 8 + 4];
            float rm[8] = {m0.x, m0.y, m0.z, m0.w, m1.x, m1.y, m1.z, m1.w};
            float rn[8] = {n0.x, n0.y, n0.z, n0.w, n1.x, n1.y, n1.z, n1.w};
#pragma unroll
            for (int i = 0; i < 8; i++)
#pragma unroll
                for (int j = 0; j < 8; j++) acc[i][j] += rm[i] * rn[j];
        }
        __syncthreads();
    }

#pragma unroll
    for (int i = 0; i < 8; i++) {
        size_t r = (size_t)(row0 + tr * 8 + i) * NO + col0 + tc * 8;
#pragma unroll
        for (int j = 0; j < 8; j += 4) {
            float4 v;
            if (BR) {
                v.x = fmaxf(acc[i][j+0] + bias[col0 + tc*8 + j + 0], 0.0f);
                v.y = fmaxf(acc[i][j+1] + bias[col0 + tc*8 + j + 1], 0.0f);
                v.z = fmaxf(acc[i][j+2] + bias[col0 + tc*8 + j + 2], 0.0f);
                v.w = fmaxf(acc[i][j+3] + bias[col0 + tc*8 + j + 3], 0.0f);
            } else {
                v.x = acc[i][j+0]; v.y = acc[i][j+1]; v.z = acc[i][j+2]; v.w = acc[i][j+3];
            }
            *(float4*)&C[r + j] = v;
        }
    }
}

// ---------------- bias + relu + pooled accumulation --------------------------
__global__ void k_pool(const float* __restrict__ b2, const int* __restrict__ batch,
                       float* __restrict__ out) {
    int idx = blockIdx.x * blockDim.x + threadIdx.x;   // NN*FOUT
    if (idx >= NN * FOUT) return;
    int i = idx >> 7, f = idx & 127;
    float v = fmaxf(g_agg2[(size_t)idx] + b2[f], 0.0f);
    int g = batch[i];
    atomicAdd(&out[g * FOUT + f], v);
}

__global__ void k_div(float* __restrict__ out) {
    int idx = blockIdx.x * blockDim.x + threadIdx.x;   // NG*FOUT
    if (idx >= NG * FOUT) return;
    float c = (float)g_gcnt[idx >> 7];
    out[idx] = out[idx] / fmaxf(c, 1.0f);
}

// ---------------- launch ------------------------------------------------------
extern "C" void kernel_launch(void* const* d_in, const int* in_sizes, int n_in,
                              void* d_out, int out_size) {
    const float* chord = (const float*)d_in[0];
    const float* W1    = (const float*)d_in[1];
    const float* b1    = (const float*)d_in[2];
    const float* W2    = (const float*)d_in[3];
    const float* b2    = (const float*)d_in[4];
    const float* ea    = (const float*)d_in[5];
    const int*   nidx  = (const int*)d_in[6];
    const int*   ei    = (const int*)d_in[7];
    const int*   batch = (const int*)d_in[8];
    float* out = (float*)d_out;

    float *p_agg1, *p_h1, *p_y2;
    cudaGetSymbolAddress((void**)&p_agg1, g_agg1);
    cudaGetSymbolAddress((void**)&p_h1,   g_h1);
    cudaGetSymbolAddress((void**)&p_y2,   g_y2);

    k_init  <<<NN / 256, 256>>>(out);
    k_deg   <<<NE / 256, 256>>>(ei, ea);
    k_count <<<NN / 256, 256>>>(batch);
    k_dis   <<<NN / 256, 256>>>();
    k_bucket<<<NE / 256, 256>>>(ei, ea);
    k_gather<<<NN * 32 / 256, 256>>>(chord, nidx);
    k_agg1  <<<NN / 8, 256>>>();                        // 8 warps/block, 1 warp/node

    dim3 g1(HID / 128, NN / 128);                       // (2, 512)
    k_gemm<FIN, HID, true><<<g1, 256>>>(p_agg1, W1, b1, p_h1);

    dim3 g2(FOUT / 128, NN / 128);                      // (1, 512)
    k_gemm<HID, FOUT, false><<<g2, 256>>>(p_h1, W2, nullptr, p_y2);

    k_agg2  <<<NN / 8, 256>>>();
    k_pool  <<<(NN * FOUT) / 256, 256>>>(b2, batch, out);
    k_div   <<<(NG * FOUT) / 256, 256>>>(out);
}

// round 5
// speedup vs baseline: 1.0831x; 1.0831x over previous
#include <cuda_runtime.h>
#include <cuda_bf16.h>
#include <cstdint>

// Problem constants
#define NN   65536      // nodes
#define NE   2097152    // edges
#define FIN  128
#define HID  256
#define FOUT 128
#define NG   256        // graphs
#define CAP  128        // max in-degree bucket capacity (mean 32)

// ---------------- scratch (static device globals; no runtime alloc) ----------
__device__ float    g_deg[NN];
__device__ float    g_dis[NN];
__device__ int      g_cnt[NN];
__device__ int      g_brow [(size_t)NN * CAP];   // 32 MB
__device__ float    g_bnorm[(size_t)NN * CAP];   // 32 MB
__device__ float    g_x0   [(size_t)NN * FIN];   // 32 MB
__device__ unsigned g_agg1p[(size_t)NN * FIN];   // 32 MB  packed (bf16hi<<16)|bf16lo
__device__ unsigned g_h1p  [(size_t)NN * HID];   // 64 MB  packed
__device__ float    g_y2   [(size_t)NN * FOUT];  // 32 MB
__device__ float    g_agg2 [(size_t)NN * FOUT];  // 32 MB
__device__ int      g_gcnt[NG];

// ================= helpers ===================================================
__device__ __forceinline__ uint32_t smem_u32(const void* p) {
    uint32_t a;
    asm("{ .reg .u64 t; cvta.to.shared.u64 t, %1; cvt.u32.u64 %0, t; }" : "=r"(a) : "l"(p));
    return a;
}
__device__ __forceinline__ void ldsm4(uint32_t* r, uint32_t addr) {
    asm volatile("ldmatrix.sync.aligned.m8n8.x4.shared.b16 {%0,%1,%2,%3}, [%4];"
                 : "=r"(r[0]), "=r"(r[1]), "=r"(r[2]), "=r"(r[3]) : "r"(addr));
}
__device__ __forceinline__ void ldsm4t(uint32_t* r, uint32_t addr) {
    asm volatile("ldmatrix.sync.aligned.m8n8.x4.trans.shared.b16 {%0,%1,%2,%3}, [%4];"
                 : "=r"(r[0]), "=r"(r[1]), "=r"(r[2]), "=r"(r[3]) : "r"(addr));
}
__device__ __forceinline__ void mma_bf16(float* c, const uint32_t* a, const uint32_t* b) {
    asm volatile("mma.sync.aligned.m16n8k16.row.col.f32.bf16.bf16.f32 "
                 "{%0,%1,%2,%3}, {%4,%5,%6,%7}, {%8,%9}, {%0,%1,%2,%3};"
                 : "+f"(c[0]), "+f"(c[1]), "+f"(c[2]), "+f"(c[3])
                 : "r"(a[0]), "r"(a[1]), "r"(a[2]), "r"(a[3]), "r"(b[0]), "r"(b[1]));
}
// hi/lo bf16 split of fp32, packed (hi<<16)|lo
__device__ __forceinline__ unsigned pack_hl(float x) {
    __nv_bfloat16 h = __float2bfloat16(x);
    float hf = __bfloat162float(h);
    __nv_bfloat16 l = __float2bfloat16(x - hf);
    return ((unsigned)__bfloat16_as_ushort(h) << 16) | (unsigned)__bfloat16_as_ushort(l);
}

// ---------------- init -------------------------------------------------------
__global__ void k_init(float* __restrict__ out) {
    int i = blockIdx.x * blockDim.x + threadIdx.x;
    if (i < NN) { g_deg[i] = 1.0f; g_cnt[i] = 0; }
    if (i < NG) g_gcnt[i] = 0;
    if (i < NG * FOUT) out[i] = 0.0f;
}

__global__ void k_deg(const int* __restrict__ ei, const float* __restrict__ ea) {
    int e = blockIdx.x * blockDim.x + threadIdx.x;
    if (e >= NE) return;
    atomicAdd(&g_deg[ei[NE + e]], ea[e]);
}

__global__ void k_dis() {
    int i = blockIdx.x * blockDim.x + threadIdx.x;
    if (i < NN) g_dis[i] = rsqrtf(g_deg[i]);
}

__global__ void k_count(const int* __restrict__ batch) {
    int i = blockIdx.x * blockDim.x + threadIdx.x;
    if (i < NN) atomicAdd(&g_gcnt[batch[i]], 1);
}

__global__ void k_bucket(const int* __restrict__ ei, const float* __restrict__ ea) {
    int e = blockIdx.x * blockDim.x + threadIdx.x;
    if (e >= NE) return;
    int row = ei[e], col = ei[NE + e];
    float n = g_dis[row] * ea[e] * g_dis[col];
    int k = atomicAdd(&g_cnt[col], 1);
    if (k < CAP) {
        g_brow [(size_t)col * CAP + k] = row;
        g_bnorm[(size_t)col * CAP + k] = n;
    }
}

__global__ void k_gather(const float* __restrict__ chord, const int* __restrict__ nidx) {
    int t = blockIdx.x * blockDim.x + threadIdx.x;
    if (t >= NN * 32) return;
    int i = t >> 5, l = t & 31;
    ((float4*)g_x0)[(size_t)i * 32 + l] = ((const float4*)chord)[(size_t)nidx[i] * 32 + l];
}

// ---------------- 128-dim gather aggregation: 1 warp per node ----------------
template<bool PACK>
__device__ __forceinline__ void agg128_body(const float* __restrict__ X, void* __restrict__ Y) {
    int w = (blockIdx.x * blockDim.x + threadIdx.x) >> 5;
    if (w >= NN) return;
    int lane = threadIdx.x & 31;
    const float4* X4 = (const float4*)X;

    float d = g_dis[w];
    float s = d * d;
    float4 v = X4[(size_t)w * 32 + lane];
    float ax = v.x * s, ay = v.y * s, az = v.z * s, aw = v.w * s;

    int cnt = g_cnt[w]; if (cnt > CAP) cnt = CAP;
    const int*   br = g_brow  + (size_t)w * CAP;
    const float* bn = g_bnorm + (size_t)w * CAP;

    int k = 0;
    for (; k + 4 <= cnt; k += 4) {
        int r0 = br[k], r1 = br[k+1], r2 = br[k+2], r3 = br[k+3];
        float n0 = bn[k], n1 = bn[k+1], n2 = bn[k+2], n3 = bn[k+3];
        float4 u0 = X4[(size_t)r0 * 32 + lane];
        float4 u1 = X4[(size_t)r1 * 32 + lane];
        float4 u2 = X4[(size_t)r2 * 32 + lane];
        float4 u3 = X4[(size_t)r3 * 32 + lane];
        ax += n0*u0.x + n1*u1.x + n2*u2.x + n3*u3.x;
        ay += n0*u0.y + n1*u1.y + n2*u2.y + n3*u3.y;
        az += n0*u0.z + n1*u1.z + n2*u2.z + n3*u3.z;
        aw += n0*u0.w + n1*u1.w + n2*u2.w + n3*u3.w;
    }
    for (; k < cnt; k++) {
        int r = br[k]; float n = bn[k];
        float4 u = X4[(size_t)r * 32 + lane];
        ax += n*u.x; ay += n*u.y; az += n*u.z; aw += n*u.w;
    }
    if (PACK) {
        uint4 p; p.x = pack_hl(ax); p.y = pack_hl(ay); p.z = pack_hl(az); p.w = pack_hl(aw);
        ((uint4*)Y)[(size_t)w * 32 + lane] = p;
    } else {
        ((float4*)Y)[(size_t)w * 32 + lane] = make_float4(ax, ay, az, aw);
    }
}

__global__ void k_agg1() { agg128_body<true >(g_x0, g_agg1p); }
__global__ void k_agg2() { agg128_body<false>(g_y2, g_agg2);  }

// ================= HMMA bf16 GEMM with hi/lo split ===========================
// C[128 x 128-slab] per CTA = epi( A[M,KTOT](packed hi/lo) @ W[KTOT,NO] ).
// 8 warps as 4(m) x 2(n); warp tile 32x64; mma m16n8k16; 3 mma per logical
// (AhBh + AhBl + AlBh). SMEM: Ah/Al/Bh/Bl tiles, 32KB each, XOR swizzle
// (byte ^ ((row&7)<<4)) for conflict-free ldmatrix. K chunked by 128.
template<int KTOT, int NO, bool L1EPI>
__global__ void __launch_bounds__(256, 1) k_mmagemm(const unsigned* __restrict__ Ap,
                                                    const float* __restrict__ W,
                                                    const float* __restrict__ bias,
                                                    void* __restrict__ Out) {
    constexpr int NCH = KTOT / 128;
    extern __shared__ __align__(1024) char sm[];
    const uint32_t sb = smem_u32(sm);
    const uint32_t OFF_AH = 0, OFF_AL = 32768, OFF_BH = 65536, OFF_BL = 98304;

    const int tid   = threadIdx.x;
    const int lane  = tid & 31, wid = tid >> 5;
    const int warpM = wid & 3,  warpN = wid >> 2;
    const int row0  = blockIdx.y * 128;
    const int col0  = blockIdx.x * 128;

    float acc[2][8][4];
#pragma unroll
    for (int a = 0; a < 2; a++)
#pragma unroll
        for (int b = 0; b < 8; b++)
#pragma unroll
            for (int c = 0; c < 4; c++) acc[a][b][c] = 0.0f;

    for (int ch = 0; ch < NCH; ch++) {
        if (ch) __syncthreads();
        // ---- A tile: packed u32 -> hi/lo bf16 pair tiles ----
#pragma unroll 4
        for (int i = tid; i < 128 * 64; i += 256) {
            int r = i >> 6, kp = i & 63;
            uint2 v = *(const uint2*)&Ap[(size_t)(row0 + r) * KTOT + ch * 128 + kp * 2];
            uint32_t hi2 = (v.x >> 16)      | (v.y & 0xFFFF0000u);
            uint32_t lo2 = (v.x & 0xFFFFu)  | (v.y << 16);
            uint32_t so = (uint32_t)(r * 256 + kp * 4) ^ ((uint32_t)(r & 7) << 4);
            *(uint32_t*)(sm + OFF_AH + so) = hi2;
            *(uint32_t*)(sm + OFF_AL + so) = lo2;
        }
        // ---- B tile: W fp32 -> hi/lo bf16, row-major [k][n] ----
#pragma unroll 4
        for (int i = tid; i < 128 * 64; i += 256) {
            int k = i >> 6, np = i & 63;
            const float* wp = &W[(size_t)(ch * 128 + k) * NO + col0 + np * 2];
            float w0 = wp[0], w1 = wp[1];
            __nv_bfloat16 h0 = __float2bfloat16(w0), h1 = __float2bfloat16(w1);
            __nv_bfloat16 l0 = __float2bfloat16(w0 - __bfloat162float(h0));
            __nv_bfloat16 l1 = __float2bfloat16(w1 - __bfloat162float(h1));
            uint32_t hi2 = (uint32_t)__bfloat16_as_ushort(h0) | ((uint32_t)__bfloat16_as_ushort(h1) << 16);
            uint32_t lo2 = (uint32_t)__bfloat16_as_ushort(l0) | ((uint32_t)__bfloat16_as_ushort(l1) << 16);
            uint32_t so = (uint32_t)(k * 256 + np * 4) ^ ((uint32_t)(k & 7) << 4);
            *(uint32_t*)(sm + OFF_BH + so) = hi2;
            *(uint32_t*)(sm + OFF_BL + so) = lo2;
        }
        __syncthreads();

        // ---- compute: 8 k-steps of 16 ----
        const int sub = lane >> 3, wi = lane & 7;
#pragma unroll
        for (int ks = 0; ks < 8; ks++) {
            const int kBase = ks * 16;
            uint32_t ah[2][4], al[2][4];
#pragma unroll
            for (int mt = 0; mt < 2; mt++) {
                int row  = warpM * 32 + mt * 16 + wi + (sub & 1) * 8;
                int kcol = kBase + (sub >> 1) * 8;
                uint32_t so = (uint32_t)(row * 256 + kcol * 2) ^ ((uint32_t)(row & 7) << 4);
                ldsm4(ah[mt], sb + OFF_AH + so);
                ldsm4(al[mt], sb + OFF_AL + so);
            }
#pragma unroll
            for (int ng = 0; ng < 4; ng++) {          // 4 groups of n16
                uint32_t bh[4], bl[4];
                int kr = kBase + (sub & 1) * 8 + wi;
                int nc = warpN * 64 + ng * 16 + (sub >> 1) * 8;
                uint32_t so = (uint32_t)(kr * 256 + nc * 2) ^ ((uint32_t)(kr & 7) << 4);
                ldsm4t(bh, sb + OFF_BH + so);
                ldsm4t(bl, sb + OFF_BL + so);
#pragma unroll
                for (int mt = 0; mt < 2; mt++)
#pragma unroll
                    for (int h = 0; h < 2; h++) {
                        int nt = ng * 2 + h;
                        mma_bf16(acc[mt][nt], ah[mt], bh + 2 * h);
                        mma_bf16(acc[mt][nt], ah[mt], bl + 2 * h);
                        mma_bf16(acc[mt][nt], al[mt], bh + 2 * h);
                    }
            }
        }
    }

    // ---- epilogue ----
    const int gr = lane >> 2, tig = lane & 3;
#pragma unroll
    for (int mt = 0; mt < 2; mt++) {
#pragma unroll
        for (int nt = 0; nt < 8; nt++) {
            int r  = row0 + warpM * 32 + mt * 16 + gr;
            int cc = col0 + warpN * 64 + nt * 8 + tig * 2;
            float* c = acc[mt][nt];
            if (L1EPI) {
                float b0 = bias[cc], b1 = bias[cc + 1];
                uint2 p0, p1;
                p0.x = pack_hl(fmaxf(c[0] + b0, 0.0f));
                p0.y = pack_hl(fmaxf(c[1] + b1, 0.0f));
                p1.x = pack_hl(fmaxf(c[2] + b0, 0.0f));
                p1.y = pack_hl(fmaxf(c[3] + b1, 0.0f));
                *(uint2*)((unsigned*)Out + (size_t)r * NO + cc)       = p0;
                *(uint2*)((unsigned*)Out + (size_t)(r + 8) * NO + cc) = p1;
            } else {
                *(float2*)((float*)Out + (size_t)r * NO + cc)       = make_float2(c[0], c[1]);
                *(float2*)((float*)Out + (size_t)(r + 8) * NO + cc) = make_float2(c[2], c[3]);
            }
        }
    }
}

// ---------------- bias + relu + pooled accumulation --------------------------
__global__ void k_pool(const float* __restrict__ b2, const int* __restrict__ batch,
                       float* __restrict__ out) {
    int idx = blockIdx.x * blockDim.x + threadIdx.x;
    if (idx >= NN * FOUT) return;
    int i = idx >> 7, f = idx & 127;
    float v = fmaxf(g_agg2[(size_t)idx] + b2[f], 0.0f);
    atomicAdd(&out[batch[i] * FOUT + f], v);
}

__global__ void k_div(float* __restrict__ out) {
    int idx = blockIdx.x * blockDim.x + threadIdx.x;
    if (idx >= NG * FOUT) return;
    float c = (float)g_gcnt[idx >> 7];
    out[idx] = out[idx] / fmaxf(c, 1.0f);
}

// ---------------- launch ------------------------------------------------------
extern "C" void kernel_launch(void* const* d_in, const int* in_sizes, int n_in,
                              void* d_out, int out_size) {
    const float* chord = (const float*)d_in[0];
    const float* W1    = (const float*)d_in[1];
    const float* b1    = (const float*)d_in[2];
    const float* W2    = (const float*)d_in[3];
    const float* b2    = (const float*)d_in[4];
    const float* ea    = (const float*)d_in[5];
    const int*   nidx  = (const int*)d_in[6];
    const int*   ei    = (const int*)d_in[7];
    const int*   batch = (const int*)d_in[8];
    float* out = (float*)d_out;

    unsigned *p_agg1p, *p_h1p;
    float    *p_y2;
    cudaGetSymbolAddress((void**)&p_agg1p, g_agg1p);
    cudaGetSymbolAddress((void**)&p_h1p,   g_h1p);
    cudaGetSymbolAddress((void**)&p_y2,    g_y2);

    const int SMEM = 128 * 1024;   // Ah/Al/Bh/Bl tiles, 32KB each
    cudaFuncSetAttribute(k_mmagemm<FIN, HID, true>,   cudaFuncAttributeMaxDynamicSharedMemorySize, SMEM);
    cudaFuncSetAttribute(k_mmagemm<HID, FOUT, false>, cudaFuncAttributeMaxDynamicSharedMemorySize, SMEM);

    k_init  <<<NN / 256, 256>>>(out);
    k_deg   <<<NE / 256, 256>>>(ei, ea);
    k_count <<<NN / 256, 256>>>(batch);
    k_dis   <<<NN / 256, 256>>>();
    k_bucket<<<NE / 256, 256>>>(ei, ea);
    k_gather<<<NN * 32 / 256, 256>>>(chord, nidx);
    k_agg1  <<<NN / 8, 256>>>();

    dim3 g1(HID / 128, NN / 128);    // (2, 512)
    k_mmagemm<FIN, HID, true ><<<g1, 256, SMEM>>>(p_agg1p, W1, b1, p_h1p);

    dim3 g2(FOUT / 128, NN / 128);   // (1, 512)
    k_mmagemm<HID, FOUT, false><<<g2, 256, SMEM>>>(p_h1p, W2, nullptr, p_y2);

    k_agg2  <<<NN / 8, 256>>>();
    k_pool  <<<(NN * FOUT) / 256, 256>>>(b2, batch, out);
    k_div   <<<(NG * FOUT) / 256, 256>>>(out);
}

// round 6
// speedup vs baseline: 1.1732x; 1.0831x over previous
#include <cuda_runtime.h>
#include <cuda_bf16.h>
#include <cuda_fp16.h>
#include <cstdint>

// Problem constants
#define NN   65536      // nodes
#define NE   2097152    // edges
#define VV   1000       // chord vocab
#define FIN  128
#define HID  256
#define FOUT 128
#define NG   256        // graphs
#define CAP  128        // max in-degree bucket capacity (mean 32)

// ---------------- scratch (static device globals; no runtime alloc) ----------
__device__ float    g_deg[NN];
__device__ float    g_dis[NN];
__device__ int      g_cnt[NN];
__device__ int      g_brow [(size_t)NN * CAP];   // 32 MB
__device__ float    g_bnorm[(size_t)NN * CAP];   // 32 MB
__device__ __half   g_chord16[(size_t)VV * FIN]; // 256 KB (L1-resident gather table)
__device__ unsigned g_agg1p[(size_t)NN * FIN];   // 32 MB  packed (bf16hi<<16)|bf16lo
__device__ unsigned g_h1p  [(size_t)NN * HID];   // 64 MB  packed
__device__ __half   g_y2h  [(size_t)NN * FOUT];  // 16 MB  fp16 layer-2 pre-agg
__device__ float    g_agg2 [(size_t)NN * FOUT];  // 32 MB
__device__ int      g_gcnt[NG];

// ================= helpers ===================================================
__device__ __forceinline__ uint32_t smem_u32(const void* p) {
    uint32_t a;
    asm("{ .reg .u64 t; cvta.to.shared.u64 t, %1; cvt.u32.u64 %0, t; }" : "=r"(a) : "l"(p));
    return a;
}
__device__ __forceinline__ void ldsm4(uint32_t* r, uint32_t addr) {
    asm volatile("ldmatrix.sync.aligned.m8n8.x4.shared.b16 {%0,%1,%2,%3}, [%4];"
                 : "=r"(r[0]), "=r"(r[1]), "=r"(r[2]), "=r"(r[3]) : "r"(addr));
}
__device__ __forceinline__ void ldsm4t(uint32_t* r, uint32_t addr) {
    asm volatile("ldmatrix.sync.aligned.m8n8.x4.trans.shared.b16 {%0,%1,%2,%3}, [%4];"
                 : "=r"(r[0]), "=r"(r[1]), "=r"(r[2]), "=r"(r[3]) : "r"(addr));
}
__device__ __forceinline__ void mma_bf16(float* c, const uint32_t* a, const uint32_t* b) {
    asm volatile("mma.sync.aligned.m16n8k16.row.col.f32.bf16.bf16.f32 "
                 "{%0,%1,%2,%3}, {%4,%5,%6,%7}, {%8,%9}, {%0,%1,%2,%3};"
                 : "+f"(c[0]), "+f"(c[1]), "+f"(c[2]), "+f"(c[3])
                 : "r"(a[0]), "r"(a[1]), "r"(a[2]), "r"(a[3]), "r"(b[0]), "r"(b[1]));
}
// hi/lo bf16 split of fp32, packed (hi<<16)|lo
__device__ __forceinline__ unsigned pack_hl(float x) {
    __nv_bfloat16 h = __float2bfloat16(x);
    float hf = __bfloat162float(h);
    __nv_bfloat16 l = __float2bfloat16(x - hf);
    return ((unsigned)__bfloat16_as_ushort(h) << 16) | (unsigned)__bfloat16_as_ushort(l);
}

// ---------------- init: scalars + chord->fp16 table --------------------------
__global__ void k_init(float* __restrict__ out, const float* __restrict__ chord) {
    int i = blockIdx.x * blockDim.x + threadIdx.x;    // 131072 threads
    if (i < NN) { g_deg[i] = 1.0f; g_cnt[i] = 0; }
    if (i < NG) g_gcnt[i] = 0;
    if (i < NG * FOUT) out[i] = 0.0f;
    if (i < VV * FIN) g_chord16[i] = __float2half_rn(chord[i]);
}

__global__ void k_deg(const int* __restrict__ ei, const float* __restrict__ ea) {
    int e = blockIdx.x * blockDim.x + threadIdx.x;
    if (e >= NE) return;
    atomicAdd(&g_deg[ei[NE + e]], ea[e]);
}

__global__ void k_dis(const int* __restrict__ batch) {
    int i = blockIdx.x * blockDim.x + threadIdx.x;
    if (i >= NN) return;
    g_dis[i] = rsqrtf(g_deg[i]);
    atomicAdd(&g_gcnt[batch[i]], 1);
}

__global__ void k_bucket(const int* __restrict__ ei, const float* __restrict__ ea) {
    int e = blockIdx.x * blockDim.x + threadIdx.x;
    if (e >= NE) return;
    int row = ei[e], col = ei[NE + e];
    float n = g_dis[row] * ea[e] * g_dis[col];
    int k = atomicAdd(&g_cnt[col], 1);
    if (k < CAP) {
        g_brow [(size_t)col * CAP + k] = row;
        g_bnorm[(size_t)col * CAP + k] = n;
    }
}

// ---------------- agg1: gather fp16 vocab table (L1-hot), 1 warp/node --------
__global__ void k_agg1(const int* __restrict__ nidx) {
    int w = (blockIdx.x * blockDim.x + threadIdx.x) >> 5;
    if (w >= NN) return;
    int lane = threadIdx.x & 31;
    const uint2* T = (const uint2*)g_chord16;          // row = 32 uint2 (4 halfs/lane)

    float d = g_dis[w];
    float s = d * d;
    int vs = nidx[w];
    uint2 u = T[(size_t)vs * 32 + lane];
    float2 f0 = __half22float2(*(__half2*)&u.x);
    float2 f1 = __half22float2(*(__half2*)&u.y);
    float ax = f0.x * s, ay = f0.y * s, az = f1.x * s, aw = f1.y * s;

    int cnt = g_cnt[w]; if (cnt > CAP) cnt = CAP;
    const int*   br = g_brow  + (size_t)w * CAP;
    const float* bn = g_bnorm + (size_t)w * CAP;

    int k = 0;
    for (; k + 4 <= cnt; k += 4) {
        int r0 = br[k], r1 = br[k+1], r2 = br[k+2], r3 = br[k+3];
        float n0 = bn[k], n1 = bn[k+1], n2 = bn[k+2], n3 = bn[k+3];
        int v0 = nidx[r0], v1 = nidx[r1], v2 = nidx[r2], v3 = nidx[r3];
        uint2 u0 = T[(size_t)v0 * 32 + lane];
        uint2 u1 = T[(size_t)v1 * 32 + lane];
        uint2 u2 = T[(size_t)v2 * 32 + lane];
        uint2 u3 = T[(size_t)v3 * 32 + lane];
        float2 a0 = __half22float2(*(__half2*)&u0.x), b0 = __half22float2(*(__half2*)&u0.y);
        float2 a1 = __half22float2(*(__half2*)&u1.x), b1 = __half22float2(*(__half2*)&u1.y);
        float2 a2 = __half22float2(*(__half2*)&u2.x), b2 = __half22float2(*(__half2*)&u2.y);
        float2 a3 = __half22float2(*(__half2*)&u3.x), b3 = __half22float2(*(__half2*)&u3.y);
        ax += n0*a0.x + n1*a1.x + n2*a2.x + n3*a3.x;
        ay += n0*a0.y + n1*a1.y + n2*a2.y + n3*a3.y;
        az += n0*b0.x + n1*b1.x + n2*b2.x + n3*b3.x;
        aw += n0*b0.y + n1*b1.y + n2*b2.y + n3*b3.y;
    }
    for (; k < cnt; k++) {
        int r = br[k]; float n = bn[k];
        int v = nidx[r];
        uint2 u2v = T[(size_t)v * 32 + lane];
        float2 a = __half22float2(*(__half2*)&u2v.x), b = __half22float2(*(__half2*)&u2v.y);
        ax += n*a.x; ay += n*a.y; az += n*b.x; aw += n*b.y;
    }
    uint4 p; p.x = pack_hl(ax); p.y = pack_hl(ay); p.z = pack_hl(az); p.w = pack_hl(aw);
    ((uint4*)g_agg1p)[(size_t)w * 32 + lane] = p;
}

// ---------------- agg2: gather fp16 y2 rows, 1 warp/node ---------------------
__global__ void k_agg2() {
    int w = (blockIdx.x * blockDim.x + threadIdx.x) >> 5;
    if (w >= NN) return;
    int lane = threadIdx.x & 31;
    const uint2* T = (const uint2*)g_y2h;

    float d = g_dis[w];
    float s = d * d;
    uint2 u = T[(size_t)w * 32 + lane];
    float2 f0 = __half22float2(*(__half2*)&u.x);
    float2 f1 = __half22float2(*(__half2*)&u.y);
    float ax = f0.x * s, ay = f0.y * s, az = f1.x * s, aw = f1.y * s;

    int cnt = g_cnt[w]; if (cnt > CAP) cnt = CAP;
    const int*   br = g_brow  + (size_t)w * CAP;
    const float* bn = g_bnorm + (size_t)w * CAP;

    int k = 0;
    for (; k + 4 <= cnt; k += 4) {
        int r0 = br[k], r1 = br[k+1], r2 = br[k+2], r3 = br[k+3];
        float n0 = bn[k], n1 = bn[k+1], n2 = bn[k+2], n3 = bn[k+3];
        uint2 u0 = T[(size_t)r0 * 32 + lane];
        uint2 u1 = T[(size_t)r1 * 32 + lane];
        uint2 u2 = T[(size_t)r2 * 32 + lane];
        uint2 u3 = T[(size_t)r3 * 32 + lane];
        float2 a0 = __half22float2(*(__half2*)&u0.x), b0 = __half22float2(*(__half2*)&u0.y);
        float2 a1 = __half22float2(*(__half2*)&u1.x), b1 = __half22float2(*(__half2*)&u1.y);
        float2 a2 = __half22float2(*(__half2*)&u2.x), b2 = __half22float2(*(__half2*)&u2.y);
        float2 a3 = __half22float2(*(__half2*)&u3.x), b3 = __half22float2(*(__half2*)&u3.y);
        ax += n0*a0.x + n1*a1.x + n2*a2.x + n3*a3.x;
        ay += n0*a0.y + n1*a1.y + n2*a2.y + n3*a3.y;
        az += n0*b0.x + n1*b1.x + n2*b2.x + n3*b3.x;
        aw += n0*b0.y + n1*b1.y + n2*b2.y + n3*b3.y;
    }
    for (; k < cnt; k++) {
        int r = br[k]; float n = bn[k];
        uint2 u2v = T[(size_t)r * 32 + lane];
        float2 a = __half22float2(*(__half2*)&u2v.x), b = __half22float2(*(__half2*)&u2v.y);
        ax += n*a.x; ay += n*a.y; az += n*b.x; aw += n*b.y;
    }
    ((float4*)g_agg2)[(size_t)w * 32 + lane] = make_float4(ax, ay, az, aw);
}

// ================= HMMA bf16 GEMM with hi/lo split ===========================
// C[128 x 128-slab] per CTA = epi( A[M,KTOT](packed hi/lo) @ W[KTOT,NO] ).
// 8 warps as 4(m) x 2(n); warp tile 32x64; mma m16n8k16; 3 mma per logical
// (AhBh + AhBl + AlBh). XOR-swizzled SMEM for conflict-free ldmatrix.
// L1EPI: true -> bias+relu, pack hi/lo u32 out; false -> raw fp16 out.
template<int KTOT, int NO, bool L1EPI>
__global__ void __launch_bounds__(256, 1) k_mmagemm(const unsigned* __restrict__ Ap,
                                                    const float* __restrict__ W,
                                                    const float* __restrict__ bias,
                                                    void* __restrict__ Out) {
    constexpr int NCH = KTOT / 128;
    extern __shared__ __align__(1024) char sm[];
    const uint32_t sb = smem_u32(sm);
    const uint32_t OFF_AH = 0, OFF_AL = 32768, OFF_BH = 65536, OFF_BL = 98304;

    const int tid   = threadIdx.x;
    const int lane  = tid & 31, wid = tid >> 5;
    const int warpM = wid & 3,  warpN = wid >> 2;
    const int row0  = blockIdx.y * 128;
    const int col0  = blockIdx.x * 128;

    float acc[2][8][4];
#pragma unroll
    for (int a = 0; a < 2; a++)
#pragma unroll
        for (int b = 0; b < 8; b++)
#pragma unroll
            for (int c = 0; c < 4; c++) acc[a][b][c] = 0.0f;

    for (int ch = 0; ch < NCH; ch++) {
        if (ch) __syncthreads();
#pragma unroll 4
        for (int i = tid; i < 128 * 64; i += 256) {
            int r = i >> 6, kp = i & 63;
            uint2 v = *(const uint2*)&Ap[(size_t)(row0 + r) * KTOT + ch * 128 + kp * 2];
            uint32_t hi2 = (v.x >> 16)      | (v.y & 0xFFFF0000u);
            uint32_t lo2 = (v.x & 0xFFFFu)  | (v.y << 16);
            uint32_t so = (uint32_t)(r * 256 + kp * 4) ^ ((uint32_t)(r & 7) << 4);
            *(uint32_t*)(sm + OFF_AH + so) = hi2;
            *(uint32_t*)(sm + OFF_AL + so) = lo2;
        }
#pragma unroll 4
        for (int i = tid; i < 128 * 64; i += 256) {
            int k = i >> 6, np = i & 63;
            const float* wp = &W[(size_t)(ch * 128 + k) * NO + col0 + np * 2];
            float w0 = wp[0], w1 = wp[1];
            __nv_bfloat16 h0 = __float2bfloat16(w0), h1 = __float2bfloat16(w1);
            __nv_bfloat16 l0 = __float2bfloat16(w0 - __bfloat162float(h0));
            __nv_bfloat16 l1 = __float2bfloat16(w1 - __bfloat162float(h1));
            uint32_t hi2 = (uint32_t)__bfloat16_as_ushort(h0) | ((uint32_t)__bfloat16_as_ushort(h1) << 16);
            uint32_t lo2 = (uint32_t)__bfloat16_as_ushort(l0) | ((uint32_t)__bfloat16_as_ushort(l1) << 16);
            uint32_t so = (uint32_t)(k * 256 + np * 4) ^ ((uint32_t)(k & 7) << 4);
            *(uint32_t*)(sm + OFF_BH + so) = hi2;
            *(uint32_t*)(sm + OFF_BL + so) = lo2;
        }
        __syncthreads();

        const int sub = lane >> 3, wi = lane & 7;
#pragma unroll
        for (int ks = 0; ks < 8; ks++) {
            const int kBase = ks * 16;
            uint32_t ah[2][4], al[2][4];
#pragma unroll
            for (int mt = 0; mt < 2; mt++) {
                int row  = warpM * 32 + mt * 16 + wi + (sub & 1) * 8;
                int kcol = kBase + (sub >> 1) * 8;
                uint32_t so = (uint32_t)(row * 256 + kcol * 2) ^ ((uint32_t)(row & 7) << 4);
                ldsm4(ah[mt], sb + OFF_AH + so);
                ldsm4(al[mt], sb + OFF_AL + so);
            }
#pragma unroll
            for (int ng = 0; ng < 4; ng++) {
                uint32_t bh[4], bl[4];
                int kr = kBase + (sub & 1) * 8 + wi;
                int nc = warpN * 64 + ng * 16 + (sub >> 1) * 8;
                uint32_t so = (uint32_t)(kr * 256 + nc * 2) ^ ((uint32_t)(kr & 7) << 4);
                ldsm4t(bh, sb + OFF_BH + so);
                ldsm4t(bl, sb + OFF_BL + so);
#pragma unroll
                for (int mt = 0; mt < 2; mt++)
#pragma unroll
                    for (int h = 0; h < 2; h++) {
                        int nt = ng * 2 + h;
                        mma_bf16(acc[mt][nt], ah[mt], bh + 2 * h);
                        mma_bf16(acc[mt][nt], ah[mt], bl + 2 * h);
                        mma_bf16(acc[mt][nt], al[mt], bh + 2 * h);
                    }
            }
        }
    }

    // ---- epilogue ----
    const int gr = lane >> 2, tig = lane & 3;
#pragma unroll
    for (int mt = 0; mt < 2; mt++) {
#pragma unroll
        for (int nt = 0; nt < 8; nt++) {
            int r  = row0 + warpM * 32 + mt * 16 + gr;
            int cc = col0 + warpN * 64 + nt * 8 + tig * 2;
            float* c = acc[mt][nt];
            if (L1EPI) {
                float b0 = bias[cc], b1 = bias[cc + 1];
                uint2 p0, p1;
                p0.x = pack_hl(fmaxf(c[0] + b0, 0.0f));
                p0.y = pack_hl(fmaxf(c[1] + b1, 0.0f));
                p1.x = pack_hl(fmaxf(c[2] + b0, 0.0f));
                p1.y = pack_hl(fmaxf(c[3] + b1, 0.0f));
                *(uint2*)((unsigned*)Out + (size_t)r * NO + cc)       = p0;
                *(uint2*)((unsigned*)Out + (size_t)(r + 8) * NO + cc) = p1;
            } else {
                __half2 q0 = __floats2half2_rn(c[0], c[1]);
                __half2 q1 = __floats2half2_rn(c[2], c[3]);
                *(__half2*)((__half*)Out + (size_t)r * NO + cc)       = q0;
                *(__half2*)((__half*)Out + (size_t)(r + 8) * NO + cc) = q1;
            }
        }
    }
}

// ---------------- bias + relu + pooled accumulation --------------------------
__global__ void k_pool(const float* __restrict__ b2, const int* __restrict__ batch,
                       float* __restrict__ out) {
    int idx = blockIdx.x * blockDim.x + threadIdx.x;
    if (idx >= NN * FOUT) return;
    int i = idx >> 7, f = idx & 127;
    float v = fmaxf(g_agg2[(size_t)idx] + b2[f], 0.0f);
    atomicAdd(&out[batch[i] * FOUT + f], v);
}

__global__ void k_div(float* __restrict__ out) {
    int idx = blockIdx.x * blockDim.x + threadIdx.x;
    if (idx >= NG * FOUT) return;
    float c = (float)g_gcnt[idx >> 7];
    out[idx] = out[idx] / fmaxf(c, 1.0f);
}

// ---------------- launch ------------------------------------------------------
extern "C" void kernel_launch(void* const* d_in, const int* in_sizes, int n_in,
                              void* d_out, int out_size) {
    const float* chord = (const float*)d_in[0];
    const float* W1    = (const float*)d_in[1];
    const float* b1    = (const float*)d_in[2];
    const float* W2    = (const float*)d_in[3];
    const float* b2    = (const float*)d_in[4];
    const float* ea    = (const float*)d_in[5];
    const int*   nidx  = (const int*)d_in[6];
    const int*   ei    = (const int*)d_in[7];
    const int*   batch = (const int*)d_in[8];
    float* out = (float*)d_out;

    unsigned *p_agg1p, *p_h1p;
    __half   *p_y2h;
    cudaGetSymbolAddress((void**)&p_agg1p, g_agg1p);
    cudaGetSymbolAddress((void**)&p_h1p,   g_h1p);
    cudaGetSymbolAddress((void**)&p_y2h,   g_y2h);

    const int SMEM = 128 * 1024;
    cudaFuncSetAttribute(k_mmagemm<FIN, HID, true>,   cudaFuncAttributeMaxDynamicSharedMemorySize, SMEM);
    cudaFuncSetAttribute(k_mmagemm<HID, FOUT, false>, cudaFuncAttributeMaxDynamicSharedMemorySize, SMEM);

    k_init  <<<512, 256>>>(out, chord);               // covers VV*FIN too
    k_deg   <<<NE / 256, 256>>>(ei, ea);
    k_dis   <<<NN / 256, 256>>>(batch);
    k_bucket<<<NE / 256, 256>>>(ei, ea);
    k_agg1  <<<NN / 8, 256>>>(nidx);

    dim3 g1(HID / 128, NN / 128);    // (2, 512)
    k_mmagemm<FIN, HID, true ><<<g1, 256, SMEM>>>(p_agg1p, W1, b1, p_h1p);

    dim3 g2(FOUT / 128, NN / 128);   // (1, 512)
    k_mmagemm<HID, FOUT, false><<<g2, 256, SMEM>>>(p_h1p, W2, nullptr, p_y2h);

    k_agg2  <<<NN / 8, 256>>>();
    k_pool  <<<(NN * FOUT) / 256, 256>>>(b2, batch, out);
    k_div   <<<(NG * FOUT) / 256, 256>>>(out);
}